// round 13
// baseline (speedup 1.0000x reference)
#include <cuda_runtime.h>
#include <math.h>

typedef unsigned long long ull;
#define FULLMASK 0xFFFFFFFFu

static const int NMAX = 8192;
static const int KSEL = 16;
static const int PAD  = 128;   // INF-padded tail so scan loops can overrun

// Static device scratch (no allocation allowed).
__device__ float2 g_ch2m[NMAX + PAD];
__device__ int    g_idx[NMAX * KSEL];

// ---------------------------------------------------------------------------
// Kernel A: ch2m[a] = polynomial(ch2[a]; M1, M2); INF-fill the pad region;
// zero-init the output accumulator (d_out is poisoned before each replay).
// ---------------------------------------------------------------------------
__global__ void poly_kernel(const float* __restrict__ ch2,
                            const float* __restrict__ M1,
                            const float* __restrict__ M2,
                            float* __restrict__ out,
                            int N)
{
    int i = blockIdx.x * blockDim.x + threadIdx.x;
    if (i == 0) out[0] = 0.0f;
    if (i >= N) {
        if (i < N + PAD) {
            float inf = __int_as_float(0x7f800000);
            g_ch2m[i] = make_float2(inf, inf);
        }
        return;
    }
    float x1 = ch2[2 * i];
    float x2 = ch2[2 * i + 1];
    float a00 = __ldg(M1 + 0), a01 = __ldg(M1 + 1), a10 = __ldg(M1 + 2), a11 = __ldg(M1 + 3);
    float b00 = __ldg(M2 + 0), b01 = __ldg(M2 + 1), b10 = __ldg(M2 + 2), b11 = __ldg(M2 + 3);
    float x12 = __fmul_rn(x1, x2);
    float y1 = __fadd_rn(__fadd_rn(a00, __fmul_rn(a01, x2)),
                         __fadd_rn(__fmul_rn(a10, x1), __fmul_rn(a11, x12)));
    float y2 = __fadd_rn(__fadd_rn(b00, __fmul_rn(b01, x2)),
                         __fadd_rn(__fmul_rn(b10, x1), __fmul_rn(b11, x12)));
    g_ch2m[i] = make_float2(y1, y2);
}

// ---------------------------------------------------------------------------
// Kernel B: exact 16-NN, 2 queries per warp, 128 candidates per iteration.
// Each query's running best-32 lives as a warp-distributed sorted list of
// packed u64 (dist_bits<<32 | index); u64 ascending == (dist asc, idx asc),
// matching jax.lax.top_k tie-breaking exactly. Top-16 = lanes 0..15.
// Insertion keeps the 32 smallest seen (drops lane 31) — the top-16 prefix
// is exact as long as every candidate lex-below the CURRENT 16th is admitted;
// the stale batch threshold only over-admits, so this holds.
// ---------------------------------------------------------------------------
__device__ __forceinline__ float sqd(float px, float py, float qx, float qy)
{
    float dx = __fadd_rn(px, -qx);
    float dy = __fadd_rn(py, -qy);
    return __fmaf_rn(dy, dy, __fmul_rn(dx, dx));
}

__device__ __forceinline__ ull pack(float d, unsigned idx)
{
    return ((ull)__float_as_uint(d) << 32) | idx;
}

__device__ __forceinline__ float top16d(ull e)   // dist of rank 15
{
    return __uint_as_float((unsigned)(__shfl_sync(FULLMASK, e, 15) >> 32));
}

__device__ __forceinline__ void insert32(ull& e, ull pv, int lane)
{
    unsigned lm = __ballot_sync(FULLMASK, pv < e);
    ull up = __shfl_up_sync(FULLMASK, e, 1);
    if (lm) {
        int pos = __ffs(lm) - 1;
        if (lane == pos)      e = pv;
        else if (lane > pos)  e = up;
    }
}

// Drain a ballot mask; candidate index for source lane s is base2 + 2*s + off.
__device__ __forceinline__ void drain(unsigned m, float d, int base2, int off,
                                      ull& e, int lane)
{
    while (m) {
        int s = __ffs(m) - 1;
        m &= m - 1;
        float vd = __shfl_sync(FULLMASK, d, s);
        insert32(e, pack(vd, (unsigned)(base2 + 2 * s + off)), lane);
    }
}

__global__ void __launch_bounds__(256) knn_kernel(const float* __restrict__ ch1, int N)
{
    const int lane = threadIdx.x & 31;
    const int warp = threadIdx.x >> 5;
    const int w = blockIdx.x * 8 + warp;       // warp id: handles queries 2w, 2w+1
    const int q0 = 2 * w, q1 = 2 * w + 1;
    if (q0 >= N) return;

    const float q0x = __ldg(ch1 + 2 * q0), q0y = __ldg(ch1 + 2 * q0 + 1);
    const float q1x = __ldg(ch1 + 2 * q1), q1y = __ldg(ch1 + 2 * q1 + 1);
    const float2* __restrict__ pts = g_ch2m;
    const float4* __restrict__ p4  = (const float4*)g_ch2m;

    // --- Prefill: candidates 0..31, bitonic-sort both lists simultaneously ---
    float2 p = __ldg(&pts[lane]);
    ull e0 = pack(sqd(p.x, p.y, q0x, q0y), (unsigned)lane);
    ull e1 = pack(sqd(p.x, p.y, q1x, q1y), (unsigned)lane);
    #pragma unroll
    for (int k = 2; k <= 32; k <<= 1) {
        #pragma unroll
        for (int j = k >> 1; j >= 1; j >>= 1) {
            ull o0 = __shfl_xor_sync(FULLMASK, e0, j);
            ull o1 = __shfl_xor_sync(FULLMASK, e1, j);
            bool takeMin = (((lane & j) == 0) == ((lane & k) == 0));
            ull mn0 = (e0 < o0) ? e0 : o0, mx0 = (e0 < o0) ? o0 : e0;
            ull mn1 = (e1 < o1) ? e1 : o1, mx1 = (e1 < o1) ? o1 : e1;
            e0 = takeMin ? mn0 : mx0;
            e1 = takeMin ? mn1 : mx1;
        }
    }
    float wd0 = top16d(e0);
    float wd1 = top16d(e1);

    // --- Main scan: 128 candidates / warp-iter (2 float4 loads, 2 queries) ---
    for (int b4 = 16; b4 < N / 2; b4 += 64) {
        float4 A = __ldg(p4 + b4 + lane);
        float4 B = __ldg(p4 + b4 + 32 + lane);

        float a0q0 = sqd(A.x, A.y, q0x, q0y), a1q0 = sqd(A.z, A.w, q0x, q0y);
        float b0q0 = sqd(B.x, B.y, q0x, q0y), b1q0 = sqd(B.z, B.w, q0x, q0y);
        float a0q1 = sqd(A.x, A.y, q1x, q1y), a1q1 = sqd(A.z, A.w, q1x, q1y);
        float b0q1 = sqd(B.x, B.y, q1x, q1y), b1q1 = sqd(B.z, B.w, q1x, q1y);

        float m0 = fminf(fminf(a0q0, a1q0), fminf(b0q0, b1q0));
        float m1 = fminf(fminf(a0q1, a1q1), fminf(b0q1, b1q1));

        if (__any_sync(FULLMASK, (m0 <= wd0) | (m1 <= wd1))) {
            int baseA = 2 * b4, baseB = 2 * (b4 + 32);
            unsigned h0 = __ballot_sync(FULLMASK, m0 <= wd0);
            if (h0) {
                drain(__ballot_sync(FULLMASK, a0q0 <= wd0), a0q0, baseA, 0, e0, lane);
                drain(__ballot_sync(FULLMASK, a1q0 <= wd0), a1q0, baseA, 1, e0, lane);
                drain(__ballot_sync(FULLMASK, b0q0 <= wd0), b0q0, baseB, 0, e0, lane);
                drain(__ballot_sync(FULLMASK, b1q0 <= wd0), b1q0, baseB, 1, e0, lane);
                wd0 = top16d(e0);
            }
            unsigned h1 = __ballot_sync(FULLMASK, m1 <= wd1);
            if (h1) {
                drain(__ballot_sync(FULLMASK, a0q1 <= wd1), a0q1, baseA, 0, e1, lane);
                drain(__ballot_sync(FULLMASK, a1q1 <= wd1), a1q1, baseA, 1, e1, lane);
                drain(__ballot_sync(FULLMASK, b0q1 <= wd1), b0q1, baseB, 0, e1, lane);
                drain(__ballot_sync(FULLMASK, b1q1 <= wd1), b1q1, baseB, 1, e1, lane);
                wd1 = top16d(e1);
            }
        }
    }

    if (lane < KSEL) {
        g_idx[q0 * KSEL + lane] = (int)(e0 & 0xFFFFFFFFull);
        g_idx[q1 * KSEL + lane] = (int)(e1 & 0xFFFFFFFFull);
    }
}

// ---------------------------------------------------------------------------
// Kernel C: scrambled gather + exp/log reduction, block partial -> atomicAdd.
// expD[q] = (1/N) * sum_{p<16} exp(-sqd(ch2m[idx[q/16 + (N/16)*p][q%16]], ch1[q]) / 4.5)
// out = -sum_q log(expD[q])   (expD provably nonzero for this data range)
// ---------------------------------------------------------------------------
__global__ void __launch_bounds__(256) reduce_kernel(const float* __restrict__ ch1,
                                                     float* __restrict__ out,
                                                     int N, int NK)
{
    int q = blockIdx.x * blockDim.x + threadIdx.x;
    float term = 0.0f;
    if (q < N) {
        float qx = ch1[2 * q];
        float qy = ch1[2 * q + 1];
        int s  = q % KSEL;
        int r0 = q / KSEL;
        float acc = 0.0f;
        #pragma unroll
        for (int pp = 0; pp < KSEL; ++pp) {
            int a = __ldg(&g_idx[(r0 + pp * NK) * KSEL + s]);
            float2 pa = g_ch2m[a];
            float d = sqd(pa.x, pa.y, qx, qy);
            acc += __expf(d * (-1.0f / 4.5f));
        }
        float expD = acc / (float)N;
        if (expD != 0.0f) term = -__logf(expD);
    }
    __shared__ float red[256];
    red[threadIdx.x] = term;
    __syncthreads();
    #pragma unroll
    for (int off = 128; off > 0; off >>= 1) {
        if (threadIdx.x < off) red[threadIdx.x] += red[threadIdx.x + off];
        __syncthreads();
    }
    if (threadIdx.x == 0) atomicAdd(out, red[0]);
}

// ---------------------------------------------------------------------------
extern "C" void kernel_launch(void* const* d_in, const int* in_sizes, int n_in,
                              void* d_out, int out_size)
{
    const float* ch1 = (const float*)d_in[0];
    const float* ch2 = (const float*)d_in[1];
    const float* M1  = (const float*)d_in[2];
    const float* M2  = (const float*)d_in[3];
    float* out = (float*)d_out;
    int N = in_sizes[0] / 2;   // 8192

    poly_kernel<<<(N + PAD + 255) / 256, 256>>>(ch2, M1, M2, out, N);

    int nwarps = N / 2;                 // 2 queries per warp
    int nb = (nwarps + 7) / 8;          // 8 warps per block
    knn_kernel<<<nb, 256>>>(ch1, N);

    int nc = (N + 255) / 256;           // 32 blocks
    reduce_kernel<<<nc, 256>>>(ch1, out, N, N / KSEL);
}

// round 14
// speedup vs baseline: 1.0032x; 1.0032x over previous
#include <cuda_runtime.h>
#include <math.h>

typedef unsigned long long ull;
#define FULLMASK 0xFFFFFFFFu

static const int NMAX = 8192;
static const int KSEL = 16;
static const int PAD  = 128;   // INF-padded tail so scan loops can overrun

// Static device scratch (no allocation allowed).
__device__ float2 g_ch2m[NMAX + PAD];
__device__ int    g_idx[NMAX * KSEL];

// ---------------------------------------------------------------------------
// Kernel A: ch2m[a] = polynomial(ch2[a]; M1, M2); INF-fill the pad region;
// zero-init the output accumulator (d_out is poisoned before each replay).
// ---------------------------------------------------------------------------
__global__ void poly_kernel(const float* __restrict__ ch2,
                            const float* __restrict__ M1,
                            const float* __restrict__ M2,
                            float* __restrict__ out,
                            int N)
{
    int i = blockIdx.x * blockDim.x + threadIdx.x;
    if (i == 0) out[0] = 0.0f;
    if (i >= N) {
        if (i < N + PAD) {
            float inf = __int_as_float(0x7f800000);
            g_ch2m[i] = make_float2(inf, inf);
        }
        return;
    }
    float x1 = ch2[2 * i];
    float x2 = ch2[2 * i + 1];
    float a00 = __ldg(M1 + 0), a01 = __ldg(M1 + 1), a10 = __ldg(M1 + 2), a11 = __ldg(M1 + 3);
    float b00 = __ldg(M2 + 0), b01 = __ldg(M2 + 1), b10 = __ldg(M2 + 2), b11 = __ldg(M2 + 3);
    float x12 = __fmul_rn(x1, x2);
    float y1 = __fadd_rn(__fadd_rn(a00, __fmul_rn(a01, x2)),
                         __fadd_rn(__fmul_rn(a10, x1), __fmul_rn(a11, x12)));
    float y2 = __fadd_rn(__fadd_rn(b00, __fmul_rn(b01, x2)),
                         __fadd_rn(__fmul_rn(b10, x1), __fmul_rn(b11, x12)));
    g_ch2m[i] = make_float2(y1, y2);
}

// ---------------------------------------------------------------------------
// Kernel B: exact 16-NN, 2 queries per warp, 128 candidates per iteration.
// Each query's running best-32 lives as a warp-distributed sorted list of
// packed u64 (dist_bits<<32 | index); u64 ascending == (dist asc, idx asc),
// matching jax.lax.top_k tie-breaking exactly. Top-16 = lanes 0..15.
// Insertion keeps the 32 smallest seen (drops lane 31) — the top-16 prefix
// is exact as long as every candidate lex-below the CURRENT 16th is admitted;
// the stale batch threshold only over-admits, so this holds.
// ---------------------------------------------------------------------------
__device__ __forceinline__ float sqd(float px, float py, float qx, float qy)
{
    float dx = __fadd_rn(px, -qx);
    float dy = __fadd_rn(py, -qy);
    return __fmaf_rn(dy, dy, __fmul_rn(dx, dx));
}

__device__ __forceinline__ ull pack(float d, unsigned idx)
{
    return ((ull)__float_as_uint(d) << 32) | idx;
}

__device__ __forceinline__ float top16d(ull e)   // dist of rank 15
{
    return __uint_as_float((unsigned)(__shfl_sync(FULLMASK, e, 15) >> 32));
}

__device__ __forceinline__ void insert32(ull& e, ull pv, int lane)
{
    unsigned lm = __ballot_sync(FULLMASK, pv < e);
    ull up = __shfl_up_sync(FULLMASK, e, 1);
    if (lm) {
        int pos = __ffs(lm) - 1;
        if (lane == pos)      e = pv;
        else if (lane > pos)  e = up;
    }
}

// Drain a ballot mask; candidate index for source lane s is base2 + 2*s + off.
__device__ __forceinline__ void drain(unsigned m, float d, int base2, int off,
                                      ull& e, int lane)
{
    while (m) {
        int s = __ffs(m) - 1;
        m &= m - 1;
        float vd = __shfl_sync(FULLMASK, d, s);
        insert32(e, pack(vd, (unsigned)(base2 + 2 * s + off)), lane);
    }
}

__global__ void __launch_bounds__(256) knn_kernel(const float* __restrict__ ch1, int N)
{
    const int lane = threadIdx.x & 31;
    const int warp = threadIdx.x >> 5;
    const int w = blockIdx.x * 8 + warp;       // warp id: handles queries 2w, 2w+1
    const int q0 = 2 * w, q1 = 2 * w + 1;
    if (q0 >= N) return;

    const float q0x = __ldg(ch1 + 2 * q0), q0y = __ldg(ch1 + 2 * q0 + 1);
    const float q1x = __ldg(ch1 + 2 * q1), q1y = __ldg(ch1 + 2 * q1 + 1);
    const float2* __restrict__ pts = g_ch2m;
    const float4* __restrict__ p4  = (const float4*)g_ch2m;

    // --- Prefill: candidates 0..31, bitonic-sort both lists simultaneously ---
    float2 p = __ldg(&pts[lane]);
    ull e0 = pack(sqd(p.x, p.y, q0x, q0y), (unsigned)lane);
    ull e1 = pack(sqd(p.x, p.y, q1x, q1y), (unsigned)lane);
    #pragma unroll
    for (int k = 2; k <= 32; k <<= 1) {
        #pragma unroll
        for (int j = k >> 1; j >= 1; j >>= 1) {
            ull o0 = __shfl_xor_sync(FULLMASK, e0, j);
            ull o1 = __shfl_xor_sync(FULLMASK, e1, j);
            bool takeMin = (((lane & j) == 0) == ((lane & k) == 0));
            ull mn0 = (e0 < o0) ? e0 : o0, mx0 = (e0 < o0) ? o0 : e0;
            ull mn1 = (e1 < o1) ? e1 : o1, mx1 = (e1 < o1) ? o1 : e1;
            e0 = takeMin ? mn0 : mx0;
            e1 = takeMin ? mn1 : mx1;
        }
    }
    float wd0 = top16d(e0);
    float wd1 = top16d(e1);

    // --- Main scan: 128 candidates / warp-iter (2 float4 loads, 2 queries) ---
    for (int b4 = 16; b4 < N / 2; b4 += 64) {
        float4 A = __ldg(p4 + b4 + lane);
        float4 B = __ldg(p4 + b4 + 32 + lane);

        float a0q0 = sqd(A.x, A.y, q0x, q0y), a1q0 = sqd(A.z, A.w, q0x, q0y);
        float b0q0 = sqd(B.x, B.y, q0x, q0y), b1q0 = sqd(B.z, B.w, q0x, q0y);
        float a0q1 = sqd(A.x, A.y, q1x, q1y), a1q1 = sqd(A.z, A.w, q1x, q1y);
        float b0q1 = sqd(B.x, B.y, q1x, q1y), b1q1 = sqd(B.z, B.w, q1x, q1y);

        float m0 = fminf(fminf(a0q0, a1q0), fminf(b0q0, b1q0));
        float m1 = fminf(fminf(a0q1, a1q1), fminf(b0q1, b1q1));

        if (__any_sync(FULLMASK, (m0 <= wd0) | (m1 <= wd1))) {
            int baseA = 2 * b4, baseB = 2 * (b4 + 32);
            unsigned h0 = __ballot_sync(FULLMASK, m0 <= wd0);
            if (h0) {
                drain(__ballot_sync(FULLMASK, a0q0 <= wd0), a0q0, baseA, 0, e0, lane);
                drain(__ballot_sync(FULLMASK, a1q0 <= wd0), a1q0, baseA, 1, e0, lane);
                drain(__ballot_sync(FULLMASK, b0q0 <= wd0), b0q0, baseB, 0, e0, lane);
                drain(__ballot_sync(FULLMASK, b1q0 <= wd0), b1q0, baseB, 1, e0, lane);
                wd0 = top16d(e0);
            }
            unsigned h1 = __ballot_sync(FULLMASK, m1 <= wd1);
            if (h1) {
                drain(__ballot_sync(FULLMASK, a0q1 <= wd1), a0q1, baseA, 0, e1, lane);
                drain(__ballot_sync(FULLMASK, a1q1 <= wd1), a1q1, baseA, 1, e1, lane);
                drain(__ballot_sync(FULLMASK, b0q1 <= wd1), b0q1, baseB, 0, e1, lane);
                drain(__ballot_sync(FULLMASK, b1q1 <= wd1), b1q1, baseB, 1, e1, lane);
                wd1 = top16d(e1);
            }
        }
    }

    if (lane < KSEL) {
        g_idx[q0 * KSEL + lane] = (int)(e0 & 0xFFFFFFFFull);
        g_idx[q1 * KSEL + lane] = (int)(e1 & 0xFFFFFFFFull);
    }
}

// ---------------------------------------------------------------------------
// Kernel C: scrambled gather + exp/log reduction, block partial -> atomicAdd.
// expD[q] = (1/N) * sum_{p<16} exp(-sqd(ch2m[idx[q/16 + (N/16)*p][q%16]], ch1[q]) / 4.5)
// out = -sum_q log(expD[q])   (expD provably nonzero for this data range)
// ---------------------------------------------------------------------------
__global__ void __launch_bounds__(256) reduce_kernel(const float* __restrict__ ch1,
                                                     float* __restrict__ out,
                                                     int N, int NK)
{
    int q = blockIdx.x * blockDim.x + threadIdx.x;
    float term = 0.0f;
    if (q < N) {
        float qx = ch1[2 * q];
        float qy = ch1[2 * q + 1];
        int s  = q % KSEL;
        int r0 = q / KSEL;
        float acc = 0.0f;
        #pragma unroll
        for (int pp = 0; pp < KSEL; ++pp) {
            int a = __ldg(&g_idx[(r0 + pp * NK) * KSEL + s]);
            float2 pa = g_ch2m[a];
            float d = sqd(pa.x, pa.y, qx, qy);
            acc += __expf(d * (-1.0f / 4.5f));
        }
        float expD = acc / (float)N;
        if (expD != 0.0f) term = -__logf(expD);
    }
    __shared__ float red[256];
    red[threadIdx.x] = term;
    __syncthreads();
    #pragma unroll
    for (int off = 128; off > 0; off >>= 1) {
        if (threadIdx.x < off) red[threadIdx.x] += red[threadIdx.x + off];
        __syncthreads();
    }
    if (threadIdx.x == 0) atomicAdd(out, red[0]);
}

// ---------------------------------------------------------------------------
extern "C" void kernel_launch(void* const* d_in, const int* in_sizes, int n_in,
                              void* d_out, int out_size)
{
    const float* ch1 = (const float*)d_in[0];
    const float* ch2 = (const float*)d_in[1];
    const float* M1  = (const float*)d_in[2];
    const float* M2  = (const float*)d_in[3];
    float* out = (float*)d_out;
    int N = in_sizes[0] / 2;   // 8192

    poly_kernel<<<(N + PAD + 255) / 256, 256>>>(ch2, M1, M2, out, N);

    int nwarps = N / 2;                 // 2 queries per warp
    int nb = (nwarps + 7) / 8;          // 8 warps per block
    knn_kernel<<<nb, 256>>>(ch1, N);

    int nc = (N + 255) / 256;           // 32 blocks
    reduce_kernel<<<nc, 256>>>(ch1, out, N, N / KSEL);
}